// round 16
// baseline (speedup 1.0000x reference)
#include <cuda_runtime.h>
#include <cuda_bf16.h>
#include <cstdint>

#define UNITS 256
#define NUM_BUCKETS 501
#define LB (-17.0f)
#define UB (8.0f)
#define STEPF 0.05f
#define INV_STEP 20.0f
#define RESIDUE (-17.05f)
#define NLOG2E (-1.4426950408889634f)
// tiny-path threshold: logit_max <= -4  <=>  log2e*logit_max <= -4*log2e
#define TINY_M2_MAX (-5.7707801635558535f)

#define PARAM_BLOCKS 32
#define MAIN_BLOCKS 1024

// General-path table: per (unit, bucket):
//   .x = STEP * csum_exc[u][j] + RESIDUE + b[u]
//   .y = w[u][j] = relu(v[u][j])
__device__ float2 g_tab[UNITS * NUM_BUCKETS];

// Per-unit fast-path params (exp-domain folded):
//   if w[u,:] constant:  .x = -log2(e)*w (<= 0),  .y = -log2(e)*(w*(STEP-LB)+RESIDUE+b)
//   else:                .x = +1.0f (flag > 0), .y unused
__device__ float2 g_param[UNITS];

// Release flag: param blocks atomicAdd(+1) after publishing. Monotonic across
// graph replays — params are recomputed to identical values every launch, so
// waiters passing on a prior launch's count still read correct (identical)
// params. Deterministic: same inputs -> same work -> same output每 call.
__device__ int g_ready;

__device__ __forceinline__ float ex2f(float x) {
    float r;
    asm("ex2.approx.f32 %0, %1;" : "=f"(r) : "f"(x));
    return r;
}
__device__ __forceinline__ float rcpf(float x) {
    float r;
    asm("rcp.approx.f32 %0, %1;" : "=f"(r) : "f"(x));
    return r;
}

// ---------------------------------------------------------------------------
// Fused kernel.
// Blocks 0..31: warp-per-unit param build (8 warps x 32 blocks = 256 units),
//   publish via __threadfence + atomicAdd, then retire (frees SM slots).
// Blocks 32..1055: spin on g_ready (volatile L2 poll, nanosleep throttle),
//   then stream: tiny sigmoid fast path (FFMA, EX2, FFMA per element),
//   unroll x2, default loads (x stays L2-resident across replays),
//   evict-first stores.
// Deadlock-safe: lowest block ids are scheduled in wave 1; waiters in later
// waves observe the flag already set.
// ---------------------------------------------------------------------------
__global__ void __launch_bounds__(256)
iso_fused_kernel(const float4* __restrict__ x4,
                 const float* __restrict__ v,
                 const float* __restrict__ b,
                 float4* __restrict__ out4,
                 int rows) {
    const int bid = blockIdx.x;
    const int tid = threadIdx.x;

    if (bid < PARAM_BLOCKS) {
        // ---------------- param build (R15 kernel A body) ----------------
        const int lane = tid & 31;
        const int warp = tid >> 5;
        const int u    = bid * 8 + warp;
        const float* vu = v + u * NUM_BUCKETS;

        float mn = 1e30f, mx = -1e30f;
        #pragma unroll
        for (int k = 0; k < 16; ++k) {
            const int i = k * 32 + lane;
            if (i < NUM_BUCKETS) {
                const float ww = fmaxf(vu[i], 0.0f);
                mn = fminf(mn, ww);
                mx = fmaxf(mx, ww);
            }
        }
        #pragma unroll
        for (int o = 16; o > 0; o >>= 1) {
            mn = fminf(mn, __shfl_xor_sync(0xffffffffu, mn, o));
            mx = fmaxf(mx, __shfl_xor_sync(0xffffffffu, mx, o));
        }

        const float bu = __shfl_sync(0xffffffffu, (lane == 0) ? b[u] : 0.0f, 0);

        if (mn == mx) {
            if (lane == 0) {
                const float wc = mn;
                const float c  = fmaf(wc, STEPF - LB, RESIDUE + bu);
                float2 p;
                p.x = NLOG2E * wc;   // <= 0
                p.y = NLOG2E * c;
                g_param[u] = p;
            }
        } else {
            if (lane == 0) {
                float2 p; p.x = 1.0f; p.y = 0.0f;   // flag: general path
                g_param[u] = p;
            }
            // cold fallback: lane-chunk scan, write table
            float w[16], local[16];
            float run = 0.0f;
            #pragma unroll
            for (int k = 0; k < 16; ++k) {
                const int i = lane * 16 + k;
                const float ww = (i < NUM_BUCKETS) ? fmaxf(vu[i], 0.0f) : 0.0f;
                w[k] = ww;
                run += ww;
                local[k] = run;
            }
            float tot = run;
            #pragma unroll
            for (int o = 1; o < 32; o <<= 1) {
                float n = __shfl_up_sync(0xffffffffu, tot, o);
                if (lane >= o) tot += n;
            }
            const float prefix = tot - run;
            #pragma unroll
            for (int k = 0; k < 16; ++k) {
                const int i = lane * 16 + k;
                if (i < NUM_BUCKETS) {
                    const float exc = prefix + local[k] - w[k];
                    float2 e;
                    e.x = STEPF * exc + RESIDUE + bu;
                    e.y = w[k];
                    g_tab[u * NUM_BUCKETS + i] = e;
                }
            }
        }

        __syncthreads();
        if (tid == 0) {
            __threadfence();               // release params/table
            atomicAdd(&g_ready, 1);
        }
        return;                            // retire, free the SM slot
    }

    // ---------------- main streaming blocks ----------------
    if (tid == 0) {
        while (*(volatile int*)&g_ready < PARAM_BLOCKS) __nanosleep(100);
        __threadfence();                   // acquire
    }
    __syncthreads();

    const int mbid    = bid - PARAM_BLOCKS;
    const int gid     = mbid * 256 + tid;
    const int col     = gid & 63;                 // float4 column (0..63)
    const int row0    = gid >> 6;
    const int rstride = (MAIN_BLOCKS * 256) >> 6; // 4096
    const int ubase   = col * 4;

    // L2-path loads: bypass any (identical-valued) stale L1 lines
    const float2 p0 = __ldcg(&g_param[ubase + 0]);
    const float2 p1 = __ldcg(&g_param[ubase + 1]);
    const float2 p2 = __ldcg(&g_param[ubase + 2]);
    const float2 p3 = __ldcg(&g_param[ubase + 3]);

    const float4* __restrict__ pin  = x4   + (size_t)row0 * 64 + col;
    float4* __restrict__       pout = out4 + (size_t)row0 * 64 + col;
    const int step = rstride * 64;

    const bool fast = (p0.x <= 0.0f) & (p1.x <= 0.0f) &
                      (p2.x <= 0.0f) & (p3.x <= 0.0f);

    if (fast) {
        // positive-domain params: m2 = log2e*logit; q = 2^m2 = e^logit
        const float pw2[4] = {-p0.x, -p1.x, -p2.x, -p3.x};  // >= 0
        const float pc2[4] = {-p0.y, -p1.y, -p2.y, -p3.y};

        bool tiny = true;
        #pragma unroll
        for (int j = 0; j < 4; ++j)
            tiny &= (fmaf(8.0f, pw2[j], pc2[j]) <= TINY_M2_MAX);

        int row = row0;
        if (tiny) {
            // sigmoid = q/(1+q) ~= q - q^2  (1 MUFU per element)
            for (; row + rstride < rows; row += 2 * rstride) {
                float4 xa = pin[0];
                float4 xb = pin[step];
                float q;
                q = ex2f(fmaf(xa.x, pw2[0], pc2[0])); xa.x = fmaf(-q, q, q);
                q = ex2f(fmaf(xa.y, pw2[1], pc2[1])); xa.y = fmaf(-q, q, q);
                q = ex2f(fmaf(xa.z, pw2[2], pc2[2])); xa.z = fmaf(-q, q, q);
                q = ex2f(fmaf(xa.w, pw2[3], pc2[3])); xa.w = fmaf(-q, q, q);
                q = ex2f(fmaf(xb.x, pw2[0], pc2[0])); xb.x = fmaf(-q, q, q);
                q = ex2f(fmaf(xb.y, pw2[1], pc2[1])); xb.y = fmaf(-q, q, q);
                q = ex2f(fmaf(xb.z, pw2[2], pc2[2])); xb.z = fmaf(-q, q, q);
                q = ex2f(fmaf(xb.w, pw2[3], pc2[3])); xb.w = fmaf(-q, q, q);
                __stcs(pout,        xa);
                __stcs(pout + step, xb);
                pin  += 2 * step;
                pout += 2 * step;
            }
            for (; row < rows; row += rstride) {
                float4 xa = *pin;
                float q;
                q = ex2f(fmaf(xa.x, pw2[0], pc2[0])); xa.x = fmaf(-q, q, q);
                q = ex2f(fmaf(xa.y, pw2[1], pc2[1])); xa.y = fmaf(-q, q, q);
                q = ex2f(fmaf(xa.z, pw2[2], pc2[2])); xa.z = fmaf(-q, q, q);
                q = ex2f(fmaf(xa.w, pw2[3], pc2[3])); xa.w = fmaf(-q, q, q);
                __stcs(pout, xa);
                pin  += step;
                pout += step;
            }
        } else {
            const float nw[4] = {p0.x, p1.x, p2.x, p3.x};
            const float nc[4] = {p0.y, p1.y, p2.y, p3.y};
            for (; row + rstride < rows; row += 2 * rstride) {
                float4 xa = pin[0];
                float4 xb = pin[step];
                xa.x = rcpf(1.0f + ex2f(fmaf(xa.x, nw[0], nc[0])));
                xa.y = rcpf(1.0f + ex2f(fmaf(xa.y, nw[1], nc[1])));
                xa.z = rcpf(1.0f + ex2f(fmaf(xa.z, nw[2], nc[2])));
                xa.w = rcpf(1.0f + ex2f(fmaf(xa.w, nw[3], nc[3])));
                xb.x = rcpf(1.0f + ex2f(fmaf(xb.x, nw[0], nc[0])));
                xb.y = rcpf(1.0f + ex2f(fmaf(xb.y, nw[1], nc[1])));
                xb.z = rcpf(1.0f + ex2f(fmaf(xb.z, nw[2], nc[2])));
                xb.w = rcpf(1.0f + ex2f(fmaf(xb.w, nw[3], nc[3])));
                __stcs(pout,        xa);
                __stcs(pout + step, xb);
                pin  += 2 * step;
                pout += 2 * step;
            }
            for (; row < rows; row += rstride) {
                float4 xa = *pin;
                xa.x = rcpf(1.0f + ex2f(fmaf(xa.x, nw[0], nc[0])));
                xa.y = rcpf(1.0f + ex2f(fmaf(xa.y, nw[1], nc[1])));
                xa.z = rcpf(1.0f + ex2f(fmaf(xa.z, nw[2], nc[2])));
                xa.w = rcpf(1.0f + ex2f(fmaf(xa.w, nw[3], nc[3])));
                __stcs(pout, xa);
                pin  += step;
                pout += step;
            }
        }
    } else {
        for (int row = row0; row < rows; row += rstride) {
            const float4 xv = *pin;
            float xin[4] = {xv.x, xv.y, xv.z, xv.w};
            float oo[4];
            #pragma unroll
            for (int j = 0; j < 4; ++j) {
                const float xc = fminf(fmaxf(xin[j], LB + 1e-9f), UB - 1e-9f);
                const float2 pj = (j == 0) ? p0 : (j == 1) ? p1 : (j == 2) ? p2 : p3;
                if (pj.x <= 0.0f) {
                    oo[j] = rcpf(1.0f + ex2f(fmaf(xc, pj.x, pj.y)));
                } else {
                    float t = xc - LB + STEPF;            // in (0.05, 25.05)
                    int idx = (int)(t * INV_STEP);
                    idx = min(idx, NUM_BUCKETS - 1);
                    float delta = t - (float)idx * STEPF;
                    float2 tw = __ldcg(&g_tab[(ubase + j) * NUM_BUCKETS + idx]);
                    float logit = fmaf(delta, tw.y, tw.x);
                    oo[j] = rcpf(1.0f + ex2f(NLOG2E * logit));
                }
            }
            __stcs(pout, make_float4(oo[0], oo[1], oo[2], oo[3]));
            pin  += step;
            pout += step;
        }
    }
}

// ---------------------------------------------------------------------------
extern "C" void kernel_launch(void* const* d_in, const int* in_sizes, int n_in,
                              void* d_out, int out_size) {
    const float* x = (const float*)d_in[0];   // (65536, 256)
    const float* v = (const float*)d_in[1];   // (256, 501)
    const float* b = (const float*)d_in[2];   // (256,)
    float* out = (float*)d_out;

    const int total = in_sizes[0];            // 65536 * 256
    const int rows  = total / UNITS;          // 65536

    // 32 param blocks (retire early) + 1024 main blocks
    iso_fused_kernel<<<PARAM_BLOCKS + MAIN_BLOCKS, 256>>>(
        (const float4*)x, v, b, (float4*)out, rows);
}

// round 17
// speedup vs baseline: 1.4901x; 1.4901x over previous
#include <cuda_runtime.h>
#include <cuda_bf16.h>
#include <cstdint>

#define UNITS 256
#define NUM_BUCKETS 501
#define LB (-17.0f)
#define UB (8.0f)
#define STEPF 0.05f
#define INV_STEP 20.0f
#define RESIDUE (-17.05f)
#define NLOG2E (-1.4426950408889634f)
// tiny-path threshold: logit_max <= -4  <=>  log2e*logit_max <= -4*log2e
#define TINY_M2_MAX (-5.7707801635558535f)

// General-path table: per (unit, bucket):
//   .x = STEP * csum_exc[u][j] + RESIDUE + b[u]
//   .y = w[u][j] = relu(v[u][j])
__device__ float2 g_tab[UNITS * NUM_BUCKETS];

// Per-unit fast-path params (exp-domain folded):
//   if w[u,:] constant:  .x = -log2(e)*w (<= 0),  .y = -log2(e)*(w*(STEP-LB)+RESIDUE+b)
//   else:                .x = +1.0f (flag > 0), .y unused
__device__ float2 g_param[UNITS];

__device__ __forceinline__ float ex2f(float x) {
    float r;
    asm("ex2.approx.f32 %0, %1;" : "=f"(r) : "f"(x));
    return r;
}
__device__ __forceinline__ float rcpf(float x) {
    float r;
    asm("rcp.approx.f32 %0, %1;" : "=f"(r) : "f"(x));
    return r;
}

// ---------------------------------------------------------------------------
// Kernel A (R15 version — no spills): warp-per-unit param build.
// Hot path (constant w): stride-32 coalesced reads, 2 registers of state,
// shuffle reduce — no arrays, no syncs. Cold path reloads v and builds table.
// 32 blocks x 256 threads (8 warps); warp handles one unit.
// ---------------------------------------------------------------------------
__global__ void build_params_kernel(const float* __restrict__ v,
                                    const float* __restrict__ b) {
    const int lane = threadIdx.x & 31;
    const int warp = threadIdx.x >> 5;
    const int u    = blockIdx.x * 8 + warp;

    const float* vu = v + u * NUM_BUCKETS;

    float mn = 1e30f, mx = -1e30f;
    #pragma unroll
    for (int k = 0; k < 16; ++k) {
        const int i = k * 32 + lane;
        if (i < NUM_BUCKETS) {
            const float ww = fmaxf(vu[i], 0.0f);
            mn = fminf(mn, ww);
            mx = fmaxf(mx, ww);
        }
    }
    #pragma unroll
    for (int o = 16; o > 0; o >>= 1) {
        mn = fminf(mn, __shfl_xor_sync(0xffffffffu, mn, o));
        mx = fmaxf(mx, __shfl_xor_sync(0xffffffffu, mx, o));
    }

    const float bu = __shfl_sync(0xffffffffu, (lane == 0) ? b[u] : 0.0f, 0);

    if (mn == mx) {
        if (lane == 0) {
            const float wc = mn;
            const float c  = fmaf(wc, STEPF - LB, RESIDUE + bu);
            float2 p;
            p.x = NLOG2E * wc;   // <= 0
            p.y = NLOG2E * c;
            g_param[u] = p;
        }
        return;
    }

    if (lane == 0) {
        float2 p; p.x = 1.0f; p.y = 0.0f;   // flag: general path
        g_param[u] = p;
    }

    // cold fallback: lane-chunk scan, write table
    float w[16], local[16];
    float run = 0.0f;
    #pragma unroll
    for (int k = 0; k < 16; ++k) {
        const int i = lane * 16 + k;
        const float ww = (i < NUM_BUCKETS) ? fmaxf(vu[i], 0.0f) : 0.0f;
        w[k] = ww;
        run += ww;
        local[k] = run;
    }
    float tot = run;
    #pragma unroll
    for (int o = 1; o < 32; o <<= 1) {
        float n = __shfl_up_sync(0xffffffffu, tot, o);
        if (lane >= o) tot += n;
    }
    const float prefix = tot - run;
    #pragma unroll
    for (int k = 0; k < 16; ++k) {
        const int i = lane * 16 + k;
        if (i < NUM_BUCKETS) {
            const float exc = prefix + local[k] - w[k];
            float2 e;
            e.x = STEPF * exc + RESIDUE + bu;
            e.y = w[k];
            g_tab[u * NUM_BUCKETS + i] = e;
        }
    }
}

// ---------------------------------------------------------------------------
// Kernel B (R14 version — measured-best main: 18.78us): tiny sigmoid fast
// path (FFMA, EX2, FFMA per element; 1 MUFU), unroll x2, default loads
// (x L2-resident across replays), evict-first stores, grid = one wave.
// ---------------------------------------------------------------------------
__global__ void __launch_bounds__(256)
iso_main_kernel(const float4* __restrict__ x4,
                float4* __restrict__ out4,
                int rows) {
    const int gid     = blockIdx.x * 256 + threadIdx.x;
    const int col     = gid & 63;                 // float4 column (0..63)
    const int row0    = gid >> 6;
    const int rstride = (gridDim.x * 256) >> 6;
    const int ubase   = col * 4;

    const float2 p0 = g_param[ubase + 0];
    const float2 p1 = g_param[ubase + 1];
    const float2 p2 = g_param[ubase + 2];
    const float2 p3 = g_param[ubase + 3];

    const float4* __restrict__ pin  = x4   + (size_t)row0 * 64 + col;
    float4* __restrict__       pout = out4 + (size_t)row0 * 64 + col;
    const int step = rstride * 64;

    const bool fast = (p0.x <= 0.0f) & (p1.x <= 0.0f) &
                      (p2.x <= 0.0f) & (p3.x <= 0.0f);

    if (fast) {
        // positive-domain params: m2 = log2e*logit; q = 2^m2 = e^logit
        const float pw2[4] = {-p0.x, -p1.x, -p2.x, -p3.x};  // >= 0
        const float pc2[4] = {-p0.y, -p1.y, -p2.y, -p3.y};

        // tiny check: m2 increasing in x (pw2>=0); max at x=+8.
        bool tiny = true;
        #pragma unroll
        for (int j = 0; j < 4; ++j)
            tiny &= (fmaf(8.0f, pw2[j], pc2[j]) <= TINY_M2_MAX);

        int row = row0;
        if (tiny) {
            // sigmoid = q/(1+q) ~= q - q^2  (1 MUFU per element)
            for (; row + rstride < rows; row += 2 * rstride) {
                float4 xa = pin[0];
                float4 xb = pin[step];
                float q;
                q = ex2f(fmaf(xa.x, pw2[0], pc2[0])); xa.x = fmaf(-q, q, q);
                q = ex2f(fmaf(xa.y, pw2[1], pc2[1])); xa.y = fmaf(-q, q, q);
                q = ex2f(fmaf(xa.z, pw2[2], pc2[2])); xa.z = fmaf(-q, q, q);
                q = ex2f(fmaf(xa.w, pw2[3], pc2[3])); xa.w = fmaf(-q, q, q);
                q = ex2f(fmaf(xb.x, pw2[0], pc2[0])); xb.x = fmaf(-q, q, q);
                q = ex2f(fmaf(xb.y, pw2[1], pc2[1])); xb.y = fmaf(-q, q, q);
                q = ex2f(fmaf(xb.z, pw2[2], pc2[2])); xb.z = fmaf(-q, q, q);
                q = ex2f(fmaf(xb.w, pw2[3], pc2[3])); xb.w = fmaf(-q, q, q);
                __stcs(pout,        xa);
                __stcs(pout + step, xb);
                pin  += 2 * step;
                pout += 2 * step;
            }
            for (; row < rows; row += rstride) {
                float4 xa = *pin;
                float q;
                q = ex2f(fmaf(xa.x, pw2[0], pc2[0])); xa.x = fmaf(-q, q, q);
                q = ex2f(fmaf(xa.y, pw2[1], pc2[1])); xa.y = fmaf(-q, q, q);
                q = ex2f(fmaf(xa.z, pw2[2], pc2[2])); xa.z = fmaf(-q, q, q);
                q = ex2f(fmaf(xa.w, pw2[3], pc2[3])); xa.w = fmaf(-q, q, q);
                __stcs(pout, xa);
                pin  += step;
                pout += step;
            }
        } else {
            const float nw[4] = {p0.x, p1.x, p2.x, p3.x};
            const float nc[4] = {p0.y, p1.y, p2.y, p3.y};
            for (; row + rstride < rows; row += 2 * rstride) {
                float4 xa = pin[0];
                float4 xb = pin[step];
                xa.x = rcpf(1.0f + ex2f(fmaf(xa.x, nw[0], nc[0])));
                xa.y = rcpf(1.0f + ex2f(fmaf(xa.y, nw[1], nc[1])));
                xa.z = rcpf(1.0f + ex2f(fmaf(xa.z, nw[2], nc[2])));
                xa.w = rcpf(1.0f + ex2f(fmaf(xa.w, nw[3], nc[3])));
                xb.x = rcpf(1.0f + ex2f(fmaf(xb.x, nw[0], nc[0])));
                xb.y = rcpf(1.0f + ex2f(fmaf(xb.y, nw[1], nc[1])));
                xb.z = rcpf(1.0f + ex2f(fmaf(xb.z, nw[2], nc[2])));
                xb.w = rcpf(1.0f + ex2f(fmaf(xb.w, nw[3], nc[3])));
                __stcs(pout,        xa);
                __stcs(pout + step, xb);
                pin  += 2 * step;
                pout += 2 * step;
            }
            for (; row < rows; row += rstride) {
                float4 xa = *pin;
                xa.x = rcpf(1.0f + ex2f(fmaf(xa.x, nw[0], nc[0])));
                xa.y = rcpf(1.0f + ex2f(fmaf(xa.y, nw[1], nc[1])));
                xa.z = rcpf(1.0f + ex2f(fmaf(xa.z, nw[2], nc[2])));
                xa.w = rcpf(1.0f + ex2f(fmaf(xa.w, nw[3], nc[3])));
                __stcs(pout, xa);
                pin  += step;
                pout += step;
            }
        }
    } else {
        for (int row = row0; row < rows; row += rstride) {
            const float4 xv = *pin;
            float xin[4] = {xv.x, xv.y, xv.z, xv.w};
            float oo[4];
            #pragma unroll
            for (int j = 0; j < 4; ++j) {
                const float xc = fminf(fmaxf(xin[j], LB + 1e-9f), UB - 1e-9f);
                const float2 pj = (j == 0) ? p0 : (j == 1) ? p1 : (j == 2) ? p2 : p3;
                if (pj.x <= 0.0f) {
                    oo[j] = rcpf(1.0f + ex2f(fmaf(xc, pj.x, pj.y)));
                } else {
                    float t = xc - LB + STEPF;            // in (0.05, 25.05)
                    int idx = (int)(t * INV_STEP);
                    idx = min(idx, NUM_BUCKETS - 1);
                    float delta = t - (float)idx * STEPF;
                    float2 tw = __ldg(&g_tab[(ubase + j) * NUM_BUCKETS + idx]);
                    float logit = fmaf(delta, tw.y, tw.x);
                    oo[j] = rcpf(1.0f + ex2f(NLOG2E * logit));
                }
            }
            __stcs(pout, make_float4(oo[0], oo[1], oo[2], oo[3]));
            pin  += step;
            pout += step;
        }
    }
}

// ---------------------------------------------------------------------------
extern "C" void kernel_launch(void* const* d_in, const int* in_sizes, int n_in,
                              void* d_out, int out_size) {
    const float* x = (const float*)d_in[0];   // (65536, 256)
    const float* v = (const float*)d_in[1];   // (256, 501)
    const float* b = (const float*)d_in[2];   // (256,)
    float* out = (float*)d_out;

    // Warp-per-unit param build: 32 blocks x 8 warps = 256 units
    build_params_kernel<<<32, 256>>>(v, b);

    const int total = in_sizes[0];            // 65536 * 256
    const int rows  = total / UNITS;          // 65536

    // One full wave: 148 SMs x 8 resident CTAs (256 thr, 32 regs) = 1184
    const int blocks = 1184;
    iso_main_kernel<<<blocks, 256>>>((const float4*)x, (float4*)out, rows);
}